// round 11
// baseline (speedup 1.0000x reference)
#include <cuda_runtime.h>
#include <cuda_bf16.h>

// ---------------------------------------------------------------------------
// GATv2-like layer with FACTORIZED global softmax:
//   h = x @ W^T                                  [N,128]  (H=4 heads x F=32)
//   a_src[n,h] = sum_f lrelu(h[n,h,f]) * att[h,f]
//   a_dst[n,h] = sum_f lrelu(h[n,h,f]) * att[h,32+f]
//   score[e,h] = a_src[src,h] + a_dst[dst,h]  -> softmax over ALL edges+loops
//   => w[e,h] = es[src,h]*ed[dst,h] / Z_h      (separable => exact factorization)
//   out[d,h,:] = ed[d,h]/Z_h * ( es[d,h]*h[d,:] + sum_{e:dst=d} es[s,h]*h[s,:] )
// ---------------------------------------------------------------------------

#define IN_F      128
#define HEADS     4
#define OUT_F     32
#define HF        128      // HEADS*OUT_F
#define NEG_SLOPE 0.2f
#define MAX_NODES 50000

// scratch (device-global; runtime allocation forbidden)
__device__ float g_h[MAX_NODES * HF];       // 25.6 MB
__device__ float g_es[MAX_NODES * HEADS];
__device__ float g_ed[MAX_NODES * HEADS];
__device__ float g_Z[HEADS];
__device__ float g_invZ[HEADS];
__device__ int   g_is64;                    // edge-index dtype flag

// ---------------------------------------------------------------------------
// K0: detect whether the edge buffer is int64 or int32.
// int64 little-endian with values < 2^31 => every odd 32-bit word is zero.
// ---------------------------------------------------------------------------
__global__ void detect_kernel(const unsigned int* __restrict__ w)
{
    if (threadIdx.x == 0 && blockIdx.x == 0) {
        int is64 = 1;
        #pragma unroll 8
        for (int i = 0; i < 256; i++)
            if (w[2 * i + 1] != 0u) { is64 = 0; break; }
        g_is64 = is64;
        // zero the global-softmax accumulator here (stream-ordered first kernel)
        #pragma unroll
        for (int hh = 0; hh < HEADS; hh++) g_Z[hh] = 0.0f;
    }
}

// ---------------------------------------------------------------------------
// K1: h = x @ W^T, 48KB static smem. Block = 256 thr, 32 nodes x 64 cols.
// grid = (ceil(N/32), 2): blockIdx.y picks column-group cg (cols cg*64..+63).
// Swizzled W tile: WIDX(k,c) = k*64 + ((c + k) & 63) -> conflict-free ld/st.
// Each warp: 4 nodes; lane: cols (lane) and (lane+32) of the 64-col group.
// ---------------------------------------------------------------------------
#define WIDX(k, c) ((k) * 64 + (((c) + (k)) & 63))

__global__ void __launch_bounds__(256)
gemm_kernel(const float* __restrict__ x, const float* __restrict__ W, int nNodes)
{
    __shared__ float Wt[128 * 64];   // 32 KB (swizzled)
    __shared__ float xs[32 * 128];   // 16 KB
    int tid = threadIdx.x;
    int cg = blockIdx.y;             // 0 or 1

    // load W slice: c in [0,64), k in [0,128). gmem coalesced along k.
    #pragma unroll
    for (int i = tid; i < 64 * 128; i += 256) {
        int c = i >> 7, k = i & 127;
        Wt[WIDX(k, c)] = W[(cg * 64 + c) * IN_F + k];
    }
    int base = blockIdx.x * 32;
    #pragma unroll
    for (int i = tid; i < 32 * 128; i += 256) {
        int n = base + (i >> 7);
        xs[i] = (n < nNodes) ? x[n * IN_F + (i & 127)] : 0.0f;
    }
    __syncthreads();

    int warp = tid >> 5, lane = tid & 31;
    const float* xr = xs + warp * 4 * 128;

    float acc0[4] = {0.f, 0.f, 0.f, 0.f};
    float acc1[4] = {0.f, 0.f, 0.f, 0.f};

    #pragma unroll 4
    for (int k = 0; k < 128; k++) {
        float w0 = Wt[WIDX(k, lane)];
        float w1 = Wt[WIDX(k, lane + 32)];
        #pragma unroll
        for (int i = 0; i < 4; i++) {
            float xv = xr[i * 128 + k];    // broadcast within warp
            acc0[i] += xv * w0;
            acc1[i] += xv * w1;
        }
    }
    #pragma unroll
    for (int i = 0; i < 4; i++) {
        int n = base + warp * 4 + i;
        if (n < nNodes) {
            g_h[n * HF + cg * 64 + lane]      = acc0[i];
            g_h[n * HF + cg * 64 + 32 + lane] = acc1[i];
        }
    }
}

// ---------------------------------------------------------------------------
// K2: per-node attention precompute + self-loop init of out.
// Warp per node (grid-stride). Lane l holds h[n, hh*32+l] for hh=0..3.
// ---------------------------------------------------------------------------
__global__ void __launch_bounds__(256)
node_kernel(const float* __restrict__ att, float* __restrict__ out, int nNodes)
{
    __shared__ float att_sm[HEADS * 2 * OUT_F]; // 256
    __shared__ float zs[HEADS];
    int tid = threadIdx.x;
    if (tid < HEADS * 2 * OUT_F) att_sm[tid] = att[tid];
    if (tid < HEADS) zs[tid] = 0.0f;
    __syncthreads();

    int lane = tid & 31, warp = tid >> 5;
    int nwarps = gridDim.x * (blockDim.x >> 5);

    float zacc[HEADS] = {0.f, 0.f, 0.f, 0.f};

    for (int n = blockIdx.x * (blockDim.x >> 5) + warp; n < nNodes; n += nwarps) {
        float v[HEADS], pa[HEADS], pd[HEADS];
        #pragma unroll
        for (int hh = 0; hh < HEADS; hh++) {
            v[hh] = g_h[n * HF + hh * OUT_F + lane];
            float lr = v[hh] > 0.0f ? v[hh] : NEG_SLOPE * v[hh];
            pa[hh] = lr * att_sm[hh * 64 + lane];
            pd[hh] = lr * att_sm[hh * 64 + 32 + lane];
        }
        #pragma unroll
        for (int off = 16; off; off >>= 1) {
            #pragma unroll
            for (int hh = 0; hh < HEADS; hh++) {
                pa[hh] += __shfl_xor_sync(0xffffffffu, pa[hh], off);
                pd[hh] += __shfl_xor_sync(0xffffffffu, pd[hh], off);
            }
        }
        float es[HEADS], ed[HEADS];
        #pragma unroll
        for (int hh = 0; hh < HEADS; hh++) {
            es[hh] = expf(pa[hh]);
            ed[hh] = expf(pd[hh]);
        }
        if (lane == 0) {
            #pragma unroll
            for (int hh = 0; hh < HEADS; hh++) {
                g_es[n * HEADS + hh] = es[hh];
                g_ed[n * HEADS + hh] = ed[hh];
                zacc[hh] += es[hh] * ed[hh];   // self-loop Z term
            }
        }
        #pragma unroll
        for (int hh = 0; hh < HEADS; hh++)
            out[n * HF + hh * OUT_F + lane] = es[hh] * v[hh]; // self-loop init
    }
    if (lane == 0) {
        #pragma unroll
        for (int hh = 0; hh < HEADS; hh++) atomicAdd(&zs[hh], zacc[hh]);
    }
    __syncthreads();
    if (tid < HEADS) atomicAdd(&g_Z[tid], zs[tid]);
}

// ---------------------------------------------------------------------------
// K3: edge scatter + Z reduction. Warp per edge (grid-stride).
// Handles int64 OR int32 edge indices via g_is64 (uniform branch).
// Lane l covers floats [4l, 4l+4); one red.global.add.v4.f32 per lane/edge.
// ---------------------------------------------------------------------------
__global__ void __launch_bounds__(256)
edge_kernel(const void* __restrict__ ei, float* __restrict__ out,
            int nEdges, int nNodes)
{
    __shared__ float zs[HEADS];
    int tid = threadIdx.x;
    if (tid < HEADS) zs[tid] = 0.0f;
    __syncthreads();

    int lane = tid & 31, warp = tid >> 5;
    int nwarps = gridDim.x * (blockDim.x >> 5);
    const long long* e64 = (const long long*)ei;
    const int*       e32 = (const int*)ei;
    const int is64 = g_is64;

    int hh = lane >> 3;
    float zsum = 0.0f;

    for (int e = blockIdx.x * (blockDim.x >> 5) + warp; e < nEdges; e += nwarps) {
        int s, d;
        if (is64) {
            s = (int)e64[e];
            d = (int)e64[e + nEdges];
        } else {
            s = e32[e];
            d = e32[e + nEdges];
        }
        if ((unsigned)s >= (unsigned)nNodes || (unsigned)d >= (unsigned)nNodes)
            continue;   // crash-proof guard (never hit with valid inputs)
        if (lane < HEADS)
            zsum += g_es[s * HEADS + lane] * g_ed[d * HEADS + lane];
        float esv = g_es[s * HEADS + hh];
        float4 hv = *(const float4*)(g_h + s * HF + lane * 4);
        float* p = out + d * HF + lane * 4;
        asm volatile("red.global.add.v4.f32 [%0], {%1,%2,%3,%4};"
                     :: "l"(p), "f"(esv * hv.x), "f"(esv * hv.y),
                        "f"(esv * hv.z), "f"(esv * hv.w)
                     : "memory");
    }
    if (lane < HEADS) atomicAdd(&zs[lane], zsum);
    __syncthreads();
    if (tid < HEADS) atomicAdd(&g_Z[tid], zs[tid]);
}

// ---------------------------------------------------------------------------
// K4: invZ
// ---------------------------------------------------------------------------
__global__ void invz_kernel()
{
    if (threadIdx.x < HEADS) g_invZ[threadIdx.x] = 1.0f / g_Z[threadIdx.x];
}

// ---------------------------------------------------------------------------
// K5: out = out * ed[n,h] * invZ[h] + bias   (float4 elementwise)
// ---------------------------------------------------------------------------
__global__ void __launch_bounds__(256)
scale_kernel(float4* __restrict__ out4, const float* __restrict__ bias, int total4)
{
    int idx = blockIdx.x * blockDim.x + threadIdx.x;
    if (idx >= total4) return;
    int n = idx >> 5;            // 32 float4 per node row
    int j = (idx & 31) * 4;      // starting column within node
    int hh = j >> 5;             // head (constant across the float4)
    float sc = g_ed[n * HEADS + hh] * g_invZ[hh];
    float4 v = out4[idx];
    v.x = v.x * sc + bias[j + 0];
    v.y = v.y * sc + bias[j + 1];
    v.z = v.z * sc + bias[j + 2];
    v.w = v.w * sc + bias[j + 3];
    out4[idx] = v;
}

// ---------------------------------------------------------------------------
// Host: identify inputs by SIZE RANK (robust to any metadata ordering):
//   x (N*128=6.4M) > edge_index (2*E=1.6M) > W (16384) > att (256) > bias (128)
// ---------------------------------------------------------------------------
extern "C" void kernel_launch(void* const* d_in, const int* in_sizes, int n_in,
                              void* d_out, int out_size)
{
    int idx[16];
    for (int i = 0; i < n_in && i < 16; i++) idx[i] = i;
    for (int a = 0; a < n_in; a++)
        for (int b = a + 1; b < n_in; b++)
            if (in_sizes[idx[b]] > in_sizes[idx[a]]) {
                int t = idx[a]; idx[a] = idx[b]; idx[b] = t;
            }

    const float* x    = (const float*)d_in[idx[0]];
    const void*  ei   = d_in[idx[1]];
    const float* W    = (const float*)d_in[idx[2]];
    const float* att  = (const float*)d_in[idx[3]];
    const float* bias = (const float*)d_in[idx[4]];
    float* out = (float*)d_out;

    int nNodes = in_sizes[idx[0]] / IN_F;
    int nEdges = in_sizes[idx[1]] / 2;
    if (nNodes > MAX_NODES) nNodes = MAX_NODES;

    detect_kernel<<<1, 32>>>((const unsigned int*)ei);

    dim3 gemm_grid((nNodes + 31) / 32, 2);
    gemm_kernel<<<gemm_grid, 256>>>(x, W, nNodes);

    node_kernel<<<592, 256>>>(att, out, nNodes);

    edge_kernel<<<1184, 256>>>(ei, out, nEdges, nNodes);

    invz_kernel<<<1, 32>>>();

    int total4 = nNodes * (HF / 4);
    scale_kernel<<<(total4 + 255) / 256, 256>>>((float4*)out, bias, total4);
}

// round 12
// speedup vs baseline: 1.3907x; 1.3907x over previous
#include <cuda_runtime.h>
#include <cuda_bf16.h>

// ---------------------------------------------------------------------------
// GATv2-like layer, factorized global softmax + CSR edge aggregation.
//   h = x @ W^T ; a_src/a_dst per node ; score separable =>
//   w[e,h] = es[src,h]*ed[dst,h]/Z_h
//   out[d] = ed[d]/Z * ( es[d]*h[d] + sum_{in-edges} es[s]*h[s] )
// Pipeline:
//   init(detect dtype, zero deg/Z) -> transposeW -> GEMM(fused node epilogue)
//   -> hist -> scan1/2/3 -> scatter (CSR) -> edge-accumulate -> invZ -> scale
// ---------------------------------------------------------------------------

#define IN_F      128
#define HEADS     4
#define OUT_F     32
#define HF        128
#define NEG_SLOPE 0.2f
#define MAX_NODES 50000
#define MAX_EDGES 800000

__device__ float g_h[MAX_NODES * HF];        // 25.6 MB
__device__ float g_Wt[IN_F * HF];            // W transposed, k-major [k][c]
__device__ float g_es[MAX_NODES * HEADS];
__device__ float g_ed[MAX_NODES * HEADS];
__device__ float g_Z[HEADS];
__device__ float g_invZ[HEADS];
__device__ int   g_is64;

__device__ int   g_deg[MAX_NODES];
__device__ int   g_off[MAX_NODES + 1];
__device__ int   g_cursor[MAX_NODES];
__device__ int   g_bsum[256];
__device__ int   g_boff[256];
__device__ int   g_srcidx[MAX_EDGES];

// ---------------------------------------------------------------------------
// K0: detect edge dtype, zero degree histogram + Z.
// ---------------------------------------------------------------------------
__global__ void init_kernel(const unsigned int* __restrict__ w, int nNodes)
{
    int i = blockIdx.x * blockDim.x + threadIdx.x;
    for (int n = i; n < nNodes; n += gridDim.x * blockDim.x) g_deg[n] = 0;
    if (blockIdx.x == 0) {
        if (threadIdx.x < HEADS) g_Z[threadIdx.x] = 0.0f;
        if (threadIdx.x == 0) {
            int is64 = 1;
            for (int j = 0; j < 256; j++)
                if (w[2 * j + 1] != 0u) { is64 = 0; break; }
            g_is64 = is64;
        }
    }
}

// ---------------------------------------------------------------------------
// K0b: transpose W [HF,IN_F] row-major -> g_Wt[k*HF + c].
// ---------------------------------------------------------------------------
__global__ void transposeW_kernel(const float* __restrict__ W)
{
    __shared__ float t[32][33];
    int bx = blockIdx.x & 3, by = blockIdx.x >> 2;   // 4x4 tiles of 32x32
    int tx = threadIdx.x, ty = threadIdx.y;
    t[ty][tx] = W[(by * 32 + ty) * IN_F + bx * 32 + tx];
    __syncthreads();
    g_Wt[(bx * 32 + ty) * HF + by * 32 + tx] = t[tx][ty];
}

// ---------------------------------------------------------------------------
// K1: GEMM h = x @ W^T with fused attention epilogue.
// Block: 256 thr, 64 nodes x 128 cols. Warp: 8 nodes; lane: col quad 4*lane.
// W read as LDG.128 from g_Wt (L1-resident, 64KB).
// Epilogue: per-head 8-lane butterfly -> es/ed/exp, self-loop init of out,
// self Z terms, g_h write.
// ---------------------------------------------------------------------------
__global__ void __launch_bounds__(256)
gemm_fused_kernel(const float* __restrict__ x, const float* __restrict__ att,
                  float* __restrict__ out, int nNodes)
{
    __shared__ float xs[64 * 128];   // 32 KB
    __shared__ float zsm[HEADS];
    int tid = threadIdx.x;
    if (tid < HEADS) zsm[tid] = 0.0f;

    int base = blockIdx.x * 64;
    #pragma unroll
    for (int i = tid; i < 64 * 128; i += 256) {
        int n = base + (i >> 7);
        xs[i] = (n < nNodes) ? x[n * IN_F + (i & 127)] : 0.0f;
    }
    __syncthreads();

    int warp = tid >> 5, lane = tid & 31;
    const float* xr = xs + warp * 8 * 128;
    const float4* wt4 = (const float4*)g_Wt;

    float acc[8][4];
    #pragma unroll
    for (int i = 0; i < 8; i++)
        #pragma unroll
        for (int q = 0; q < 4; q++) acc[i][q] = 0.0f;

    #pragma unroll 4
    for (int k = 0; k < 128; k++) {
        float4 w4 = wt4[k * 32 + lane];       // LDG.128, L1-hot
        #pragma unroll
        for (int i = 0; i < 8; i++) {
            float xv = xr[i * 128 + k];       // LDS broadcast
            acc[i][0] += xv * w4.x;
            acc[i][1] += xv * w4.y;
            acc[i][2] += xv * w4.z;
            acc[i][3] += xv * w4.w;
        }
    }

    // ---- fused node epilogue ----
    int head = lane >> 3;
    int cb = (lane & 7) * 4;                  // col within head
    float as[4], ad[4];
    #pragma unroll
    for (int q = 0; q < 4; q++) {
        as[q] = att[head * 64 + cb + q];
        ad[q] = att[head * 64 + 32 + cb + q];
    }

    float zloc = 0.0f;
    #pragma unroll
    for (int i = 0; i < 8; i++) {
        float pa = 0.0f, pd = 0.0f;
        #pragma unroll
        for (int q = 0; q < 4; q++) {
            float v = acc[i][q];
            float lr = v > 0.0f ? v : NEG_SLOPE * v;
            pa += lr * as[q];
            pd += lr * ad[q];
        }
        // reduce within the 8-lane head group
        #pragma unroll
        for (int off = 1; off < 8; off <<= 1) {
            pa += __shfl_xor_sync(0xffffffffu, pa, off);
            pd += __shfl_xor_sync(0xffffffffu, pd, off);
        }
        float es = expf(pa), ed = expf(pd);
        int n = base + warp * 8 + i;
        if (n < nNodes) {
            if ((lane & 7) == 0) {
                g_es[n * HEADS + head] = es;
                g_ed[n * HEADS + head] = ed;
                zloc += es * ed;              // self-loop Z term
            }
            float4 hv = make_float4(acc[i][0], acc[i][1], acc[i][2], acc[i][3]);
            *(float4*)(g_h + n * HF + lane * 4) = hv;
            *(float4*)(out + n * HF + lane * 4) =
                make_float4(es * hv.x, es * hv.y, es * hv.z, es * hv.w);
        }
    }
    if ((lane & 7) == 0) atomicAdd(&zsm[head], zloc);
    __syncthreads();
    if (tid < HEADS) atomicAdd(&g_Z[tid], zsm[tid]);
}

// ---------------------------------------------------------------------------
// edge index loader (int64 or int32, uniform branch)
// ---------------------------------------------------------------------------
__device__ __forceinline__ void load_edge(const void* ei, int e, int nEdges,
                                          int is64, int& s, int& d)
{
    if (is64) {
        const long long* e64 = (const long long*)ei;
        s = (int)e64[e];
        d = (int)e64[e + nEdges];
    } else {
        const int* e32 = (const int*)ei;
        s = e32[e];
        d = e32[e + nEdges];
    }
}

// ---------------------------------------------------------------------------
// K2: histogram of destination degrees.
// ---------------------------------------------------------------------------
__global__ void hist_kernel(const void* __restrict__ ei, int nEdges, int nNodes)
{
    int e = blockIdx.x * blockDim.x + threadIdx.x;
    if (e >= nEdges) return;
    const int is64 = g_is64;
    int s, d;
    load_edge(ei, e, nEdges, is64, s, d);
    if ((unsigned)s < (unsigned)nNodes && (unsigned)d < (unsigned)nNodes)
        atomicAdd(&g_deg[d], 1);
}

// ---------------------------------------------------------------------------
// K3a: per-chunk (1024 elems) sums.
// ---------------------------------------------------------------------------
__global__ void scan1_kernel(int nNodes)
{
    int t = threadIdx.x, b = blockIdx.x;
    int i0 = b * 1024 + t * 4;
    int s = 0;
    #pragma unroll
    for (int q = 0; q < 4; q++)
        if (i0 + q < nNodes) s += g_deg[i0 + q];
    #pragma unroll
    for (int off = 16; off; off >>= 1)
        s += __shfl_xor_sync(0xffffffffu, s, off);
    __shared__ int wsum[8];
    if ((t & 31) == 0) wsum[t >> 5] = s;
    __syncthreads();
    if (t == 0) {
        int tot = 0;
        for (int w = 0; w < 8; w++) tot += wsum[w];
        g_bsum[b] = tot;
    }
}

// ---------------------------------------------------------------------------
// K3b: exclusive scan of chunk sums (<=256 chunks), single block.
// ---------------------------------------------------------------------------
__global__ void scan2_kernel(int nChunks, int nNodes)
{
    __shared__ int sd[256];
    int t = threadIdx.x;
    int v = (t < nChunks) ? g_bsum[t] : 0;
    sd[t] = v;
    __syncthreads();
    #pragma unroll
    for (int off = 1; off < 256; off <<= 1) {
        int add = (t >= off) ? sd[t - off] : 0;
        __syncthreads();
        sd[t] += add;
        __syncthreads();
    }
    g_boff[t] = sd[t] - v;                 // exclusive
    if (t == 255) g_off[nNodes] = sd[255]; // total valid-edge count
}

// ---------------------------------------------------------------------------
// K3c: intra-chunk exclusive scan -> g_off / g_cursor.
// ---------------------------------------------------------------------------
__global__ void scan3_kernel(int nNodes)
{
    int t = threadIdx.x, b = blockIdx.x;
    int lane = t & 31, warp = t >> 5;
    int i0 = b * 1024 + t * 4;
    int v[4];
    #pragma unroll
    for (int q = 0; q < 4; q++)
        v[q] = (i0 + q < nNodes) ? g_deg[i0 + q] : 0;
    int ts = v[0] + v[1] + v[2] + v[3];

    int x = ts;
    #pragma unroll
    for (int off = 1; off < 32; off <<= 1) {
        int y = __shfl_up_sync(0xffffffffu, x, off);
        if (lane >= off) x += y;
    }
    __shared__ int wsum[8];
    if (lane == 31) wsum[warp] = x;
    __syncthreads();
    if (t == 0) {
        int r = 0;
        for (int w = 0; w < 8; w++) { int tv = wsum[w]; wsum[w] = r; r += tv; }
    }
    __syncthreads();
    int run = g_boff[b] + wsum[warp] + (x - ts);
    #pragma unroll
    for (int q = 0; q < 4; q++) {
        if (i0 + q < nNodes) {
            g_off[i0 + q] = run;
            g_cursor[i0 + q] = run;
            run += v[q];
        }
    }
}

// ---------------------------------------------------------------------------
// K4: scatter src indices into CSR slots.
// ---------------------------------------------------------------------------
__global__ void scatter_kernel(const void* __restrict__ ei, int nEdges, int nNodes)
{
    int e = blockIdx.x * blockDim.x + threadIdx.x;
    if (e >= nEdges) return;
    const int is64 = g_is64;
    int s, d;
    load_edge(ei, e, nEdges, is64, s, d);
    if ((unsigned)s < (unsigned)nNodes && (unsigned)d < (unsigned)nNodes) {
        int p = atomicAdd(&g_cursor[d], 1);
        if ((unsigned)p < (unsigned)MAX_EDGES) g_srcidx[p] = s;
    }
}

// ---------------------------------------------------------------------------
// K5: edge accumulate — warp per destination node, register accumulation,
// one coalesced float4 write. Z edge terms folded in.
// ---------------------------------------------------------------------------
__global__ void __launch_bounds__(256)
edgeacc_kernel(float* __restrict__ out, int nNodes)
{
    __shared__ float zsm[HEADS];
    int tid = threadIdx.x;
    if (tid < HEADS) zsm[tid] = 0.0f;
    __syncthreads();

    int lane = tid & 31;
    int head = lane >> 3;
    int n = (blockIdx.x * blockDim.x + tid) >> 5;

    if (n < nNodes) {
        int o0 = g_off[n], o1 = g_off[n + 1];
        float4 acc = *(const float4*)(out + n * HF + lane * 4); // self init
        float zes = 0.0f;
        for (int j = o0; j < o1; j++) {
            int s = g_srcidx[j];                      // warp-uniform
            float esv = g_es[s * HEADS + head];
            zes += esv;
            float4 hv = *(const float4*)(g_h + s * HF + lane * 4);
            acc.x += esv * hv.x;
            acc.y += esv * hv.y;
            acc.z += esv * hv.z;
            acc.w += esv * hv.w;
        }
        *(float4*)(out + n * HF + lane * 4) = acc;
        if ((lane & 7) == 0)
            atomicAdd(&zsm[head], g_ed[n * HEADS + head] * zes);
    }
    __syncthreads();
    if (tid < HEADS) atomicAdd(&g_Z[tid], zsm[tid]);
}

// ---------------------------------------------------------------------------
// K6: invZ ; K7: scale + bias
// ---------------------------------------------------------------------------
__global__ void invz_kernel()
{
    if (threadIdx.x < HEADS) g_invZ[threadIdx.x] = 1.0f / g_Z[threadIdx.x];
}

__global__ void __launch_bounds__(256)
scale_kernel(float4* __restrict__ out4, const float* __restrict__ bias, int total4)
{
    int idx = blockIdx.x * blockDim.x + threadIdx.x;
    if (idx >= total4) return;
    int n = idx >> 5;
    int j = (idx & 31) * 4;
    int hh = j >> 5;
    float sc = g_ed[n * HEADS + hh] * g_invZ[hh];
    float4 v = out4[idx];
    v.x = v.x * sc + bias[j + 0];
    v.y = v.y * sc + bias[j + 1];
    v.z = v.z * sc + bias[j + 2];
    v.w = v.w * sc + bias[j + 3];
    out4[idx] = v;
}

// ---------------------------------------------------------------------------
// Host: identify inputs by SIZE RANK (order-proof):
//   x (6.4M) > edge_index (1.6M) > W (16384) > att (256) > bias (128)
// ---------------------------------------------------------------------------
extern "C" void kernel_launch(void* const* d_in, const int* in_sizes, int n_in,
                              void* d_out, int out_size)
{
    int idx[16];
    for (int i = 0; i < n_in && i < 16; i++) idx[i] = i;
    for (int a = 0; a < n_in; a++)
        for (int b = a + 1; b < n_in; b++)
            if (in_sizes[idx[b]] > in_sizes[idx[a]]) {
                int t = idx[a]; idx[a] = idx[b]; idx[b] = t;
            }

    const float* x    = (const float*)d_in[idx[0]];
    const void*  ei   = d_in[idx[1]];
    const float* W    = (const float*)d_in[idx[2]];
    const float* att  = (const float*)d_in[idx[3]];
    const float* bias = (const float*)d_in[idx[4]];
    float* out = (float*)d_out;

    int nNodes = in_sizes[idx[0]] / IN_F;
    int nEdges = in_sizes[idx[1]] / 2;
    if (nNodes > MAX_NODES) nNodes = MAX_NODES;
    if (nEdges > MAX_EDGES) nEdges = MAX_EDGES;

    init_kernel<<<64, 256>>>((const unsigned int*)ei, nNodes);

    transposeW_kernel<<<16, dim3(32, 32)>>>(W);

    int gemm_blocks = (nNodes + 63) / 64;
    gemm_fused_kernel<<<gemm_blocks, 256>>>(x, att, out, nNodes);

    int eblocks = (nEdges + 255) / 256;
    hist_kernel<<<eblocks, 256>>>(ei, nEdges, nNodes);

    int nChunks = (nNodes + 1023) / 1024;
    scan1_kernel<<<nChunks, 256>>>(nNodes);
    scan2_kernel<<<1, 256>>>(nChunks, nNodes);
    scan3_kernel<<<nChunks, 256>>>(nNodes);

    scatter_kernel<<<eblocks, 256>>>(ei, nEdges, nNodes);

    int ablocks = (nNodes * 32 + 255) / 256;
    edgeacc_kernel<<<ablocks, 256>>>(out, nNodes);

    invz_kernel<<<1, 32>>>();

    int total4 = nNodes * (HF / 4);
    scale_kernel<<<(total4 + 255) / 256, 256>>>((float4*)out, bias, total4);
}

// round 13
// speedup vs baseline: 1.4860x; 1.0686x over previous
#include <cuda_runtime.h>
#include <cuda_bf16.h>

// ---------------------------------------------------------------------------
// GATv2-like layer, factorized global softmax + CSR edge aggregation.
//   h = x @ W^T ; scores separable => w[e,h] = es[src,h]*ed[dst,h]/Z_h
//   out[d] = ed[d]*invZ * ( es[d]*h[d] + sum_{in-edges} es[s]*h[s] ) + bias
// Pipeline (7 launches):
//   prep(transposeW + zero deg/Z + dtype detect)
//   gemm_fused (h, es, ed, Z-self)
//   histz      (deg histogram + per-edge rank + Z-edge)
//   scan1      (per-1024-chunk sums)
//   scan3      (chunk-sum scan + intra-chunk scan -> off ; invZ ; total)
//   scatter    (srcidx[off[d]+rank] = s ; NO atomics)
//   edgeacc    (gather-accumulate + fused final scale + bias)
// ---------------------------------------------------------------------------

#define IN_F      128
#define HEADS     4
#define OUT_F     32
#define HF        128
#define NEG_SLOPE 0.2f
#define MAX_NODES 50000
#define MAX_EDGES 800000

__device__ float g_h[MAX_NODES * HF];        // 25.6 MB
__device__ float g_Wt[IN_F * HF];            // W^T, k-major
__device__ float g_es[MAX_NODES * HEADS];
__device__ float g_ed[MAX_NODES * HEADS];
__device__ float g_Z[HEADS];
__device__ float g_invZ[HEADS];
__device__ int   g_is64;

__device__ int   g_deg[MAX_NODES];
__device__ int   g_off[MAX_NODES + 1];
__device__ int   g_bsum[64];
__device__ int   g_rank[MAX_EDGES];
__device__ int   g_srcidx[MAX_EDGES];

// ---------------------------------------------------------------------------
// K0: prep — blocks [0,64): transpose W; blocks [64,..): zero deg;
//     block 64 also: detect dtype + zero Z.
// ---------------------------------------------------------------------------
__global__ void prep_kernel(const float* __restrict__ W,
                            const unsigned int* __restrict__ ew, int nNodes)
{
    int b = blockIdx.x, t = threadIdx.x;
    if (b < 64) {
        int i = b * 256 + t;            // i < 16384
        int c = i >> 7, k = i & 127;
        g_Wt[k * HF + c] = W[i];        // coalesced read, scattered write (64KB)
    } else {
        int i = (b - 64) * 256 + t;
        if (i < nNodes) g_deg[i] = 0;
        if (b == 64) {
            if (t < HEADS) g_Z[t] = 0.0f;
            if (t == 0) {
                int is64 = 1;
                for (int j = 0; j < 256; j++)
                    if (ew[2 * j + 1] != 0u) { is64 = 0; break; }
                g_is64 = is64;
            }
        }
    }
}

// ---------------------------------------------------------------------------
// K1: GEMM h = x @ W^T with fused attention epilogue (es, ed, Z-self).
// Block: 256 thr = 64 nodes; warp: 8 nodes; lane: col quad 4*lane.
// ---------------------------------------------------------------------------
__global__ void __launch_bounds__(256)
gemm_fused_kernel(const float* __restrict__ x, const float* __restrict__ att,
                  int nNodes)
{
    __shared__ float xs[64 * 128];   // 32 KB
    __shared__ float zsm[HEADS];
    int tid = threadIdx.x;
    if (tid < HEADS) zsm[tid] = 0.0f;

    int base = blockIdx.x * 64;
    #pragma unroll
    for (int i = tid; i < 64 * 128; i += 256) {
        int n = base + (i >> 7);
        xs[i] = (n < nNodes) ? x[n * IN_F + (i & 127)] : 0.0f;
    }
    __syncthreads();

    int warp = tid >> 5, lane = tid & 31;
    const float* xr = xs + warp * 8 * 128;
    const float4* wt4 = (const float4*)g_Wt;

    float acc[8][4];
    #pragma unroll
    for (int i = 0; i < 8; i++)
        #pragma unroll
        for (int q = 0; q < 4; q++) acc[i][q] = 0.0f;

    #pragma unroll 4
    for (int k = 0; k < 128; k++) {
        float4 w4 = wt4[k * 32 + lane];       // L1-hot LDG.128
        #pragma unroll
        for (int i = 0; i < 8; i++) {
            float xv = xr[i * 128 + k];       // LDS broadcast
            acc[i][0] += xv * w4.x;
            acc[i][1] += xv * w4.y;
            acc[i][2] += xv * w4.z;
            acc[i][3] += xv * w4.w;
        }
    }

    int head = lane >> 3;
    int cb = (lane & 7) * 4;
    float as[4], ad[4];
    #pragma unroll
    for (int q = 0; q < 4; q++) {
        as[q] = att[head * 64 + cb + q];
        ad[q] = att[head * 64 + 32 + cb + q];
    }

    float zloc = 0.0f;
    #pragma unroll
    for (int i = 0; i < 8; i++) {
        float pa = 0.0f, pd = 0.0f;
        #pragma unroll
        for (int q = 0; q < 4; q++) {
            float v = acc[i][q];
            float lr = v > 0.0f ? v : NEG_SLOPE * v;
            pa += lr * as[q];
            pd += lr * ad[q];
        }
        #pragma unroll
        for (int off = 1; off < 8; off <<= 1) {
            pa += __shfl_xor_sync(0xffffffffu, pa, off);
            pd += __shfl_xor_sync(0xffffffffu, pd, off);
        }
        float es = expf(pa), ed = expf(pd);
        int n = base + warp * 8 + i;
        if (n < nNodes) {
            if ((lane & 7) == 0) {
                g_es[n * HEADS + head] = es;
                g_ed[n * HEADS + head] = ed;
                zloc += es * ed;              // self-loop Z term
            }
            *(float4*)(g_h + n * HF + lane * 4) =
                make_float4(acc[i][0], acc[i][1], acc[i][2], acc[i][3]);
        }
    }
    if ((lane & 7) == 0) atomicAdd(&zsm[head], zloc);
    __syncthreads();
    if (tid < HEADS) atomicAdd(&g_Z[tid], zsm[tid]);
}

// ---------------------------------------------------------------------------
// edge index loader (int64 or int32, uniform branch)
// ---------------------------------------------------------------------------
__device__ __forceinline__ void load_edge(const void* ei, int e, int nEdges,
                                          int is64, int& s, int& d)
{
    if (is64) {
        const long long* e64 = (const long long*)ei;
        s = (int)e64[e];
        d = (int)e64[e + nEdges];
    } else {
        const int* e32 = (const int*)ei;
        s = e32[e];
        d = e32[e + nEdges];
    }
}

// ---------------------------------------------------------------------------
// K2: histogram + per-edge rank + Z-edge. 4 edges per thread (MLP).
// ---------------------------------------------------------------------------
__global__ void __launch_bounds__(256)
histz_kernel(const void* __restrict__ ei, int nEdges, int nNodes)
{
    __shared__ float zsm[HEADS];
    int tid = threadIdx.x;
    if (tid < HEADS) zsm[tid] = 0.0f;
    __syncthreads();

    const int is64 = g_is64;
    int base = (blockIdx.x * 256 + tid) * 4;

    int s[4], d[4];
    bool v[4];
    float4 es4[4], ed4[4];

    #pragma unroll
    for (int q = 0; q < 4; q++) {
        int e = base + q;
        v[q] = (e < nEdges);
        if (v[q]) {
            load_edge(ei, e, nEdges, is64, s[q], d[q]);
            v[q] = ((unsigned)s[q] < (unsigned)nNodes) &&
                   ((unsigned)d[q] < (unsigned)nNodes);
        }
    }
    #pragma unroll
    for (int q = 0; q < 4; q++) {
        if (v[q]) {
            es4[q] = *(const float4*)(g_es + s[q] * HEADS);
            ed4[q] = *(const float4*)(g_ed + d[q] * HEADS);
        }
    }

    float z0 = 0.f, z1 = 0.f, z2 = 0.f, z3 = 0.f;
    #pragma unroll
    for (int q = 0; q < 4; q++) {
        if (v[q]) {
            int r = atomicAdd(&g_deg[d[q]], 1);
            g_rank[base + q] = r;
            z0 += es4[q].x * ed4[q].x;
            z1 += es4[q].y * ed4[q].y;
            z2 += es4[q].z * ed4[q].z;
            z3 += es4[q].w * ed4[q].w;
        }
    }
    #pragma unroll
    for (int off = 16; off; off >>= 1) {
        z0 += __shfl_xor_sync(0xffffffffu, z0, off);
        z1 += __shfl_xor_sync(0xffffffffu, z1, off);
        z2 += __shfl_xor_sync(0xffffffffu, z2, off);
        z3 += __shfl_xor_sync(0xffffffffu, z3, off);
    }
    if ((tid & 31) == 0) {
        atomicAdd(&zsm[0], z0);
        atomicAdd(&zsm[1], z1);
        atomicAdd(&zsm[2], z2);
        atomicAdd(&zsm[3], z3);
    }
    __syncthreads();
    if (tid < HEADS) atomicAdd(&g_Z[tid], zsm[tid]);
}

// ---------------------------------------------------------------------------
// K3a: per-chunk (1024 elems) sums of g_deg.
// ---------------------------------------------------------------------------
__global__ void scan1_kernel(int nNodes)
{
    int t = threadIdx.x, b = blockIdx.x;
    int i0 = b * 1024 + t * 4;
    int sv = 0;
    #pragma unroll
    for (int q = 0; q < 4; q++)
        if (i0 + q < nNodes) sv += g_deg[i0 + q];
    #pragma unroll
    for (int off = 16; off; off >>= 1)
        sv += __shfl_xor_sync(0xffffffffu, sv, off);
    __shared__ int wsum[8];
    if ((t & 31) == 0) wsum[t >> 5] = sv;
    __syncthreads();
    if (t == 0) {
        int tot = 0;
        #pragma unroll
        for (int w = 0; w < 8; w++) tot += wsum[w];
        g_bsum[b] = tot;
    }
}

// ---------------------------------------------------------------------------
// K3b: per-chunk exclusive scan; each block redundantly scans the <=49 chunk
//      sums; block 0 also writes total and invZ.
// ---------------------------------------------------------------------------
__global__ void scan3_kernel(int nChunks, int nNodes)
{
    __shared__ int bs[64];
    __shared__ int wsum[8];
    int t = threadIdx.x, b = blockIdx.x;
    int lane = t & 31, warp = t >> 5;

    if (t < 64) bs[t] = (t < nChunks) ? g_bsum[t] : 0;
    __syncthreads();
    if (t == 0) {
        int r = 0;
        for (int i = 0; i < nChunks; i++) { int v = bs[i]; bs[i] = r; r += v; }
        if (b == 0) g_off[nNodes] = r;
    }
    if (b == 0 && t >= 32 && t < 32 + HEADS)
        g_invZ[t - 32] = 1.0f / g_Z[t - 32];   // Z final (histz+gemm done)
    __syncthreads();

    int i0 = b * 1024 + t * 4;
    int v[4];
    #pragma unroll
    for (int q = 0; q < 4; q++)
        v[q] = (i0 + q < nNodes) ? g_deg[i0 + q] : 0;
    int ts = v[0] + v[1] + v[2] + v[3];

    int xsc = ts;
    #pragma unroll
    for (int off = 1; off < 32; off <<= 1) {
        int y = __shfl_up_sync(0xffffffffu, xsc, off);
        if (lane >= off) xsc += y;
    }
    if (lane == 31) wsum[warp] = xsc;
    __syncthreads();
    if (t == 0) {
        int r = 0;
        #pragma unroll
        for (int w = 0; w < 8; w++) { int tv = wsum[w]; wsum[w] = r; r += tv; }
    }
    __syncthreads();
    int run = bs[b] + wsum[warp] + (xsc - ts);
    #pragma unroll
    for (int q = 0; q < 4; q++) {
        if (i0 + q < nNodes) {
            g_off[i0 + q] = run;
            run += v[q];
        }
    }
}

// ---------------------------------------------------------------------------
// K4: scatter — atomic-free: p = off[d] + rank[e]. 4 edges/thread.
// ---------------------------------------------------------------------------
__global__ void __launch_bounds__(256)
scatter_kernel(const void* __restrict__ ei, int nEdges, int nNodes)
{
    const int is64 = g_is64;
    int base = (blockIdx.x * 256 + threadIdx.x) * 4;
    #pragma unroll
    for (int q = 0; q < 4; q++) {
        int e = base + q;
        if (e >= nEdges) break;
        int s, d;
        load_edge(ei, e, nEdges, is64, s, d);
        if ((unsigned)s < (unsigned)nNodes && (unsigned)d < (unsigned)nNodes) {
            int p = g_off[d] + g_rank[e];
            if ((unsigned)p < (unsigned)MAX_EDGES) g_srcidx[p] = s;
        }
    }
}

// ---------------------------------------------------------------------------
// K5: edge accumulate + FUSED final scale/bias. Warp per node.
// out[n] = (es[n]*h[n] + sum es[s]*h[s]) * ed[n]*invZ + bias
// ---------------------------------------------------------------------------
__global__ void __launch_bounds__(256)
edgeacc_kernel(float* __restrict__ out, const float* __restrict__ bias,
               int nNodes)
{
    int tid = threadIdx.x;
    int lane = tid & 31;
    int head = lane >> 3;
    int n = (blockIdx.x * 256 + tid) >> 5;
    if (n >= nNodes) return;

    int o0 = g_off[n], o1 = g_off[n + 1];
    float4 b4 = *(const float4*)(bias + lane * 4);
    float sc = g_ed[n * HEADS + head] * g_invZ[head];
    float esv = g_es[n * HEADS + head];

    float4 hv = *(const float4*)(g_h + n * HF + lane * 4);
    float4 acc = make_float4(esv * hv.x, esv * hv.y, esv * hv.z, esv * hv.w);

    if (o0 < o1) {
        int s = g_srcidx[o0];                    // prefetch-style pipeline
        for (int j = o0; j < o1; j++) {
            int s_next = (j + 1 < o1) ? g_srcidx[j + 1] : 0;
            float ev = g_es[s * HEADS + head];
            float4 hs = *(const float4*)(g_h + s * HF + lane * 4);
            acc.x += ev * hs.x;
            acc.y += ev * hs.y;
            acc.z += ev * hs.z;
            acc.w += ev * hs.w;
            s = s_next;
        }
    }
    *(float4*)(out + n * HF + lane * 4) =
        make_float4(acc.x * sc + b4.x, acc.y * sc + b4.y,
                    acc.z * sc + b4.z, acc.w * sc + b4.w);
}

// ---------------------------------------------------------------------------
// Host: identify inputs by SIZE RANK (order-proof):
//   x (6.4M) > edge_index (1.6M) > W (16384) > att (256) > bias (128)
// ---------------------------------------------------------------------------
extern "C" void kernel_launch(void* const* d_in, const int* in_sizes, int n_in,
                              void* d_out, int out_size)
{
    int idx[16];
    for (int i = 0; i < n_in && i < 16; i++) idx[i] = i;
    for (int a = 0; a < n_in; a++)
        for (int b = a + 1; b < n_in; b++)
            if (in_sizes[idx[b]] > in_sizes[idx[a]]) {
                int t = idx[a]; idx[a] = idx[b]; idx[b] = t;
            }

    const float* x    = (const float*)d_in[idx[0]];
    const void*  ei   = d_in[idx[1]];
    const float* W    = (const float*)d_in[idx[2]];
    const float* att  = (const float*)d_in[idx[3]];
    const float* bias = (const float*)d_in[idx[4]];
    float* out = (float*)d_out;

    int nNodes = in_sizes[idx[0]] / IN_F;
    int nEdges = in_sizes[idx[1]] / 2;
    if (nNodes > MAX_NODES) nNodes = MAX_NODES;
    if (nEdges > MAX_EDGES) nEdges = MAX_EDGES;

    int zero_blocks = (nNodes + 255) / 256;
    prep_kernel<<<64 + zero_blocks, 256>>>(W, (const unsigned int*)ei, nNodes);

    int gemm_blocks = (nNodes + 63) / 64;
    gemm_fused_kernel<<<gemm_blocks, 256>>>(x, att, nNodes);

    int e4blocks = (nEdges + 1023) / 1024;
    histz_kernel<<<e4blocks, 256>>>(ei, nEdges, nNodes);

    int nChunks = (nNodes + 1023) / 1024;
    scan1_kernel<<<nChunks, 256>>>(nNodes);
    scan3_kernel<<<nChunks, 256>>>(nChunks, nNodes);

    scatter_kernel<<<e4blocks, 256>>>(ei, nEdges, nNodes);

    int ablocks = (nNodes * 32 + 255) / 256;
    edgeacc_kernel<<<ablocks, 256>>>(out, bias, nNodes);
}